// round 1
// baseline (speedup 1.0000x reference)
#include <cuda_runtime.h>
#include <cuda_bf16.h>
#include <cstdint>

#define N_NODES 50000
#define N_EDGES 800000
#define N_GRAPHS 256
#define HID 64
#define OUT_CLS 7
#define NEG_SLOPE 0.01f

// Output layout: logits [256*7] | reconstructed [N*1024] | original [N*1024]
#define OFF_RECON (N_GRAPHS * OUT_CLS)
#define OFF_ORIG  (OFF_RECON + N_NODES * 1024)

// ---------------- scratch (static device globals; no allocation allowed) ----------
__device__ float g_h0   [N_NODES * 3];
__device__ float g_aggr0[N_NODES * 3];
__device__ float g_h1   [N_NODES * 64];
__device__ float g_aggr1[N_NODES * 64];
__device__ float g_bufA [N_NODES * 256];   // enc: orig@we_rel ; dec: aggregated latent
__device__ float g_bufB [N_NODES * 256];   // enc: aggregated rel
__device__ float g_lat  [N_NODES * 256];   // latent
__device__ float g_pool [N_GRAPHS * 256];
__device__ float g_cnt  [N_GRAPHS];

// ---------------- helpers ---------------------------------------------------------
__device__ __forceinline__ void red_add_v4(float4* addr, float4 v) {
    asm volatile("red.global.add.v4.f32 [%0], {%1, %2, %3, %4};"
                 :: "l"(addr), "f"(v.x), "f"(v.y), "f"(v.z), "f"(v.w) : "memory");
}
__device__ __forceinline__ float lrelu(float v) { return v >= 0.f ? v : NEG_SLOPE * v; }

__global__ void zero4_kernel(float4* p, int n4) {
    int i = blockIdx.x * blockDim.x + threadIdx.x;
    if (i < n4) p[i] = make_float4(0.f, 0.f, 0.f, 0.f);
}

// ---------------- embedding lookup ------------------------------------------------
__global__ void embed_kernel(const int* __restrict__ x, const float* __restrict__ emb,
                             float* __restrict__ h0) {
    int i = blockIdx.x * blockDim.x + threadIdx.x;
    if (i < N_NODES) {
        int lab = x[i];
        const float* e = emb + lab * 3;
        float* o = h0 + i * 3;
        o[0] = e[0]; o[1] = e[1]; o[2] = e[2];
    }
}

// ---------------- 3-wide edge aggregation (conv1) ---------------------------------
__global__ void edge3_kernel(const float* __restrict__ xin, float* __restrict__ out,
                             const int* __restrict__ src, const int* __restrict__ dst) {
    int e = blockIdx.x * blockDim.x + threadIdx.x;
    if (e < N_EDGES) {
        int s = src[e], d = dst[e];
        atomicAdd(&out[d * 3 + 0], xin[s * 3 + 0]);
        atomicAdd(&out[d * 3 + 1], xin[s * 3 + 1]);
        atomicAdd(&out[d * 3 + 2], xin[s * 3 + 2]);
    }
}

// ---------------- vectorized edge aggregation (C = power-of-two multiple of 4) ----
// one thread per (edge, float4-chunk)
__global__ void edge_agg_v4(const float* __restrict__ xin, float* __restrict__ out,
                            const int* __restrict__ src, const int* __restrict__ dst,
                            int c4shift /* log2(C/4) */, int total) {
    int i = blockIdx.x * blockDim.x + threadIdx.x;
    if (i >= total) return;
    int e = i >> c4shift;
    int c = i & ((1 << c4shift) - 1);
    int s = src[e], d = dst[e];
    int c4 = 1 << c4shift;
    float4 v = reinterpret_cast<const float4*>(xin)[(size_t)s * c4 + c];
    red_add_v4(reinterpret_cast<float4*>(out) + (size_t)d * c4 + c, v);
}

// ---------------- conv1: h1 = leaky(aggr0 @ w_rel + h0 @ w_root + b) --------------
__global__ void conv1_kernel(const float* __restrict__ aggr0, const float* __restrict__ h0,
                             const float* __restrict__ w_rel, const float* __restrict__ w_root,
                             const float* __restrict__ b, float* __restrict__ h1) {
    __shared__ float swr[192], swo[192], sb[64];
    int tid = threadIdx.x;
    if (tid < 192) { swr[tid] = w_rel[tid]; swo[tid] = w_root[tid]; }
    if (tid < 64) sb[tid] = b[tid];
    __syncthreads();
    int idx = blockIdx.x * blockDim.x + tid;
    if (idx >= N_NODES * 64) return;
    int node = idx >> 6, c = idx & 63;
    float a0 = aggr0[node*3+0], a1 = aggr0[node*3+1], a2 = aggr0[node*3+2];
    float x0 = h0[node*3+0],   x1 = h0[node*3+1],   x2 = h0[node*3+2];
    float v = sb[c]
            + a0 * swr[c] + a1 * swr[64 + c] + a2 * swr[128 + c]
            + x0 * swo[c] + x1 * swo[64 + c] + x2 * swo[128 + c];
    h1[idx] = lrelu(v);
}

// ---------------- tiled SGEMM: C = act(A1@W1 + A2@W2 + add + bias) ----------------
// A row-major [M x K], W row-major [K x N]. N % 128 == 0, K % 8 == 0.
#define BM 128
#define BN 128
#define BK 8
#define TM 8
#define TN 8
__global__ void __launch_bounds__(256)
sgemm_dual(const float* __restrict__ A1, const float* __restrict__ W1, int K1,
           const float* __restrict__ A2, const float* __restrict__ W2, int K2,
           const float* __restrict__ add, const float* __restrict__ bias,
           float* __restrict__ C, int M, int N, int leaky) {
    __shared__ float As[BK][BM];
    __shared__ float Ws[BK][BN];
    int brow = blockIdx.y * BM;
    int bcol = blockIdx.x * BN;
    int tid = threadIdx.x;
    int tr = (tid >> 4) * TM;  // 0..120
    int tc = (tid & 15) * TN;  // 0..120

    float acc[TM][TN];
#pragma unroll
    for (int m = 0; m < TM; m++)
#pragma unroll
        for (int n = 0; n < TN; n++) acc[m][n] = 0.f;

    int arow = tid >> 1;
    int ak   = (tid & 1) * 4;
    int wk   = tid >> 5;
    int wn   = (tid & 31) * 4;

#pragma unroll 1
    for (int seg = 0; seg < 2; seg++) {
        const float* A = seg ? A2 : A1;
        const float* W = seg ? W2 : W1;
        int K = seg ? K2 : K1;
        if (A == nullptr) continue;
#pragma unroll 1
        for (int k0 = 0; k0 < K; k0 += BK) {
            float4 av = make_float4(0.f, 0.f, 0.f, 0.f);
            int grow = brow + arow;
            if (grow < M)
                av = *reinterpret_cast<const float4*>(A + (size_t)grow * K + k0 + ak);
            As[ak + 0][arow] = av.x;
            As[ak + 1][arow] = av.y;
            As[ak + 2][arow] = av.z;
            As[ak + 3][arow] = av.w;
            float4 wv = *reinterpret_cast<const float4*>(W + (size_t)(k0 + wk) * N + bcol + wn);
            *reinterpret_cast<float4*>(&Ws[wk][wn]) = wv;
            __syncthreads();
#pragma unroll
            for (int kk = 0; kk < BK; kk++) {
                float a[TM], b[TN];
#pragma unroll
                for (int m = 0; m < TM; m++) a[m] = As[kk][tr + m];
#pragma unroll
                for (int n = 0; n < TN; n++) b[n] = Ws[kk][tc + n];
#pragma unroll
                for (int m = 0; m < TM; m++)
#pragma unroll
                    for (int n = 0; n < TN; n++)
                        acc[m][n] = fmaf(a[m], b[n], acc[m][n]);
            }
            __syncthreads();
        }
    }

#pragma unroll
    for (int m = 0; m < TM; m++) {
        int row = brow + tr + m;
        if (row >= M) continue;
#pragma unroll
        for (int n = 0; n < TN; n += 4) {
            int col = bcol + tc + n;
            float4 v = make_float4(acc[m][n], acc[m][n+1], acc[m][n+2], acc[m][n+3]);
            if (add) {
                float4 a4 = *reinterpret_cast<const float4*>(add + (size_t)row * N + col);
                v.x += a4.x; v.y += a4.y; v.z += a4.z; v.w += a4.w;
            }
            if (bias) {
                float4 b4 = *reinterpret_cast<const float4*>(bias + col);
                v.x += b4.x; v.y += b4.y; v.z += b4.z; v.w += b4.w;
            }
            if (leaky) {
                v.x = lrelu(v.x); v.y = lrelu(v.y); v.z = lrelu(v.z); v.w = lrelu(v.w);
            }
            *reinterpret_cast<float4*>(C + (size_t)row * N + col) = v;
        }
    }
}

// ---------------- pooling + logits ------------------------------------------------
__global__ void pool_kernel(const float* __restrict__ latent, const int* __restrict__ batch,
                            float* __restrict__ pooled) {
    int i = blockIdx.x * blockDim.x + threadIdx.x;  // node*64 + c4
    if (i >= N_NODES * 64) return;
    int node = i >> 6, c = i & 63;
    int g = batch[node];
    float4 v = reinterpret_cast<const float4*>(latent)[(size_t)node * 64 + c];
    red_add_v4(reinterpret_cast<float4*>(pooled) + (size_t)g * 64 + c, v);
}

__global__ void count_kernel(const int* __restrict__ batch, float* __restrict__ counts) {
    int i = blockIdx.x * blockDim.x + threadIdx.x;
    if (i < N_NODES) atomicAdd(&counts[batch[i]], 1.0f);
}

__global__ void logits_kernel(const float* __restrict__ pooled, const float* __restrict__ counts,
                              const float* __restrict__ w_lin, const float* __restrict__ b_lin,
                              float* __restrict__ out) {
    int g = blockIdx.x;
    int o = threadIdx.x;
    if (o >= OUT_CLS) return;
    float inv = 1.0f / fmaxf(counts[g], 1.0f);
    float s = 0.f;
    const float* pr = pooled + g * 256;
    for (int k = 0; k < 256; k++) s += pr[k] * w_lin[k * OUT_CLS + o];
    out[g * OUT_CLS + o] = s * inv + b_lin[o];
}

// ---------------- host launch -----------------------------------------------------
static inline void zero_buf(float* p, int nfloats) {
    int n4 = nfloats / 4;
    zero4_kernel<<<(n4 + 255) / 256, 256>>>(reinterpret_cast<float4*>(p), n4);
}

extern "C" void kernel_launch(void* const* d_in, const int* in_sizes, int n_in,
                              void* d_out, int out_size) {
    const int*   x       = (const int*)d_in[0];
    const int*   ei      = (const int*)d_in[1];
    const int*   batch   = (const int*)d_in[2];
    const float* emb     = (const float*)d_in[3];
    const float* w1_rel  = (const float*)d_in[4];
    const float* w1_root = (const float*)d_in[5];
    const float* b1      = (const float*)d_in[6];
    const float* w2_rel  = (const float*)d_in[7];
    const float* w2_root = (const float*)d_in[8];
    const float* b2      = (const float*)d_in[9];
    const float* we_rel  = (const float*)d_in[10];
    const float* we_root = (const float*)d_in[11];
    const float* be      = (const float*)d_in[12];
    const float* wd_rel  = (const float*)d_in[13];
    const float* wd_root = (const float*)d_in[14];
    const float* bd      = (const float*)d_in[15];
    const float* w_lin   = (const float*)d_in[16];
    const float* b_lin   = (const float*)d_in[17];

    const int* src = ei;
    const int* dst = ei + N_EDGES;

    float* out    = (float*)d_out;
    float* logits = out;
    float* recon  = out + OFF_RECON;
    float* orig   = out + OFF_ORIG;

    float *h0, *aggr0, *h1, *aggr1, *bufA, *bufB, *lat, *pool, *cnt;
    cudaGetSymbolAddress((void**)&h0,    g_h0);
    cudaGetSymbolAddress((void**)&aggr0, g_aggr0);
    cudaGetSymbolAddress((void**)&h1,    g_h1);
    cudaGetSymbolAddress((void**)&aggr1, g_aggr1);
    cudaGetSymbolAddress((void**)&bufA,  g_bufA);
    cudaGetSymbolAddress((void**)&bufB,  g_bufB);
    cudaGetSymbolAddress((void**)&lat,   g_lat);
    cudaGetSymbolAddress((void**)&pool,  g_pool);
    cudaGetSymbolAddress((void**)&cnt,   g_cnt);

    // ---- embed + conv1 ----
    embed_kernel<<<(N_NODES + 255) / 256, 256>>>(x, emb, h0);
    zero_buf(aggr0, N_NODES * 3);  // 150000 % 4 == 0
    edge3_kernel<<<(N_EDGES + 255) / 256, 256>>>(h0, aggr0, src, dst);
    conv1_kernel<<<(N_NODES * 64 + 255) / 256, 256>>>(aggr0, h0, w1_rel, w1_root, b1, h1);

    // ---- conv2: original = leaky(aggr(h1)@w2_rel + h1@w2_root + b2) ----
    zero_buf(aggr1, N_NODES * 64);
    {
        int total = N_EDGES * 16;  // C=64 -> 16 float4 per edge
        edge_agg_v4<<<(total + 255) / 256, 256>>>(h1, aggr1, src, dst, 4, total);
    }
    {
        dim3 grid(1024 / BN, (N_NODES + BM - 1) / BM);
        sgemm_dual<<<grid, 256>>>(aggr1, w2_rel, 64, h1, w2_root, 64,
                                  nullptr, b2, orig, N_NODES, 1024, 1);
    }

    // ---- enc: latent = leaky(aggr(orig@we_rel) + orig@we_root + be) ----
    {
        dim3 grid(256 / BN, (N_NODES + BM - 1) / BM);
        sgemm_dual<<<grid, 256>>>(orig, we_rel, 1024, nullptr, nullptr, 0,
                                  nullptr, nullptr, bufA, N_NODES, 256, 0);
    }
    zero_buf(bufB, N_NODES * 256);
    {
        int total = N_EDGES * 64;  // C=256 -> 64 float4 per edge
        edge_agg_v4<<<(total + 255) / 256, 256>>>(bufA, bufB, src, dst, 6, total);
    }
    {
        dim3 grid(256 / BN, (N_NODES + BM - 1) / BM);
        sgemm_dual<<<grid, 256>>>(orig, we_root, 1024, nullptr, nullptr, 0,
                                  bufB, be, lat, N_NODES, 256, 1);
    }

    // ---- pool + logits ----
    zero_buf(pool, N_GRAPHS * 256);
    zero_buf(cnt, N_GRAPHS);
    pool_kernel<<<(N_NODES * 64 + 255) / 256, 256>>>(lat, batch, pool);
    count_kernel<<<(N_NODES + 255) / 256, 256>>>(batch, cnt);
    logits_kernel<<<N_GRAPHS, 32>>>(pool, cnt, w_lin, b_lin, logits);

    // ---- dec: recon = leaky(aggr(latent)@wd_rel + latent@wd_root + bd) ----
    zero_buf(bufA, N_NODES * 256);
    {
        int total = N_EDGES * 64;
        edge_agg_v4<<<(total + 255) / 256, 256>>>(lat, bufA, src, dst, 6, total);
    }
    {
        dim3 grid(1024 / BN, (N_NODES + BM - 1) / BM);
        sgemm_dual<<<grid, 256>>>(bufA, wd_rel, 256, lat, wd_root, 256,
                                  nullptr, bd, recon, N_NODES, 1024, 1);
    }
}

// round 2
// speedup vs baseline: 1.4401x; 1.4401x over previous
#include <cuda_runtime.h>
#include <cuda_bf16.h>
#include <cstdint>

#define N_NODES 50000
#define N_EDGES 800000
#define N_GRAPHS 256
#define HID 64
#define OUT_CLS 7
#define NEG_SLOPE 0.01f

// Output layout: logits [256*7] | reconstructed [N*1024] | original [N*1024]
#define OFF_RECON (N_GRAPHS * OUT_CLS)
#define OFF_ORIG  (OFF_RECON + N_NODES * 1024)

// ---------------- scratch (static device globals; no allocation allowed) ----------
__device__ float g_h0   [N_NODES * 3];
__device__ float g_aggr0[N_NODES * 3];
__device__ float g_h1   [N_NODES * 64];
__device__ float g_aggr1[N_NODES * 64];
__device__ float g_bufA [N_NODES * 256];   // enc: orig@we_rel ; dec: aggregated latent
__device__ float g_bufB [N_NODES * 256];   // enc: aggregated rel
__device__ float g_lat  [N_NODES * 256];   // latent
__device__ float g_pool [N_GRAPHS * 256];
__device__ float g_cnt  [N_GRAPHS];

// ---------------- helpers ---------------------------------------------------------
__device__ __forceinline__ void red_add_v4(float4* addr, float4 v) {
    asm volatile("red.global.add.v4.f32 [%0], {%1, %2, %3, %4};"
                 :: "l"(addr), "f"(v.x), "f"(v.y), "f"(v.z), "f"(v.w) : "memory");
}
__device__ __forceinline__ float lrelu(float v) { return v >= 0.f ? v : NEG_SLOPE * v; }

__device__ __forceinline__ uint32_t pack_bf16(float x, float y) {
    __nv_bfloat162 t = __floats2bfloat162_rn(x, y);
    return *reinterpret_cast<uint32_t*>(&t);
}

__device__ __forceinline__ void mma_bf16(float* d, const uint32_t* a, const uint32_t* b) {
    asm volatile(
        "mma.sync.aligned.m16n8k16.row.col.f32.bf16.bf16.f32 "
        "{%0,%1,%2,%3}, {%4,%5,%6,%7}, {%8,%9}, {%0,%1,%2,%3};"
        : "+f"(d[0]), "+f"(d[1]), "+f"(d[2]), "+f"(d[3])
        : "r"(a[0]), "r"(a[1]), "r"(a[2]), "r"(a[3]), "r"(b[0]), "r"(b[1]));
}

__global__ void zero4_kernel(float4* p, int n4) {
    int i = blockIdx.x * blockDim.x + threadIdx.x;
    if (i < n4) p[i] = make_float4(0.f, 0.f, 0.f, 0.f);
}

// ---------------- embedding lookup ------------------------------------------------
__global__ void embed_kernel(const int* __restrict__ x, const float* __restrict__ emb,
                             float* __restrict__ h0) {
    int i = blockIdx.x * blockDim.x + threadIdx.x;
    if (i < N_NODES) {
        int lab = x[i];
        const float* e = emb + lab * 3;
        float* o = h0 + i * 3;
        o[0] = e[0]; o[1] = e[1]; o[2] = e[2];
    }
}

// ---------------- 3-wide edge aggregation (conv1) ---------------------------------
__global__ void edge3_kernel(const float* __restrict__ xin, float* __restrict__ out,
                             const int* __restrict__ src, const int* __restrict__ dst) {
    int e = blockIdx.x * blockDim.x + threadIdx.x;
    if (e < N_EDGES) {
        int s = src[e], d = dst[e];
        atomicAdd(&out[d * 3 + 0], xin[s * 3 + 0]);
        atomicAdd(&out[d * 3 + 1], xin[s * 3 + 1]);
        atomicAdd(&out[d * 3 + 2], xin[s * 3 + 2]);
    }
}

// ---------------- vectorized edge aggregation (C = power-of-two multiple of 4) ----
__global__ void edge_agg_v4(const float* __restrict__ xin, float* __restrict__ out,
                            const int* __restrict__ src, const int* __restrict__ dst,
                            int c4shift /* log2(C/4) */, int total) {
    int i = blockIdx.x * blockDim.x + threadIdx.x;
    if (i >= total) return;
    int e = i >> c4shift;
    int c = i & ((1 << c4shift) - 1);
    int s = src[e], d = dst[e];
    int c4 = 1 << c4shift;
    float4 v = reinterpret_cast<const float4*>(xin)[(size_t)s * c4 + c];
    red_add_v4(reinterpret_cast<float4*>(out) + (size_t)d * c4 + c, v);
}

// ---------------- conv1: h1 = leaky(aggr0 @ w_rel + h0 @ w_root + b) --------------
__global__ void conv1_kernel(const float* __restrict__ aggr0, const float* __restrict__ h0,
                             const float* __restrict__ w_rel, const float* __restrict__ w_root,
                             const float* __restrict__ b, float* __restrict__ h1) {
    __shared__ float swr[192], swo[192], sb[64];
    int tid = threadIdx.x;
    if (tid < 192) { swr[tid] = w_rel[tid]; swo[tid] = w_root[tid]; }
    if (tid < 64) sb[tid] = b[tid];
    __syncthreads();
    int idx = blockIdx.x * blockDim.x + tid;
    if (idx >= N_NODES * 64) return;
    int node = idx >> 6, c = idx & 63;
    float a0 = aggr0[node*3+0], a1 = aggr0[node*3+1], a2 = aggr0[node*3+2];
    float x0 = h0[node*3+0],   x1 = h0[node*3+1],   x2 = h0[node*3+2];
    float v = sb[c]
            + a0 * swr[c] + a1 * swr[64 + c] + a2 * swr[128 + c]
            + x0 * swo[c] + x1 * swo[64 + c] + x2 * swo[128 + c];
    h1[idx] = lrelu(v);
}

// ---------------- bf16-split tensor-core GEMM -------------------------------------
// C = act(A1@W1 + A2@W2 + add + bias), fp32 in/out, Markidis 3-product bf16 split.
// A row-major [M x K], W row-major [K x N]. K % 32 == 0, N % 64 == 0.
#define BM 128
#define BN 64
#define BK 32
#define SROW 40   // bf16 per smem row (32 + 8 pad) -> 20 words, conflict-free frags

__global__ void __launch_bounds__(256)
gemm_bf16_dual(const float* __restrict__ A1, const float* __restrict__ W1, int K1,
               const float* __restrict__ A2, const float* __restrict__ W2, int K2,
               const float* __restrict__ add, const float* __restrict__ bias,
               float* __restrict__ C, int M, int N, int leaky) {
    __shared__ __nv_bfloat16 AsH[BM * SROW];
    __shared__ __nv_bfloat16 AsL[BM * SROW];
    __shared__ __nv_bfloat16 BsH[BN * SROW];
    __shared__ __nv_bfloat16 BsL[BN * SROW];
    uint32_t* AsH32 = reinterpret_cast<uint32_t*>(AsH);
    uint32_t* AsL32 = reinterpret_cast<uint32_t*>(AsL);
    uint32_t* BsH32 = reinterpret_cast<uint32_t*>(BsH);
    uint32_t* BsL32 = reinterpret_cast<uint32_t*>(BsL);

    int tid = threadIdx.x;
    int lane = tid & 31, wid = tid >> 5;
    int wm = (wid & 3) * 32;   // 4 warps over 128 rows
    int wn = (wid >> 2) * 32;  // 2 warps over 64 cols
    int brow = blockIdx.y * BM;
    int bcol = blockIdx.x * BN;

    float acc[2][4][4];
#pragma unroll
    for (int mt = 0; mt < 2; mt++)
#pragma unroll
        for (int nt = 0; nt < 4; nt++)
#pragma unroll
            for (int r = 0; r < 4; r++) acc[mt][nt][r] = 0.f;

#pragma unroll 1
    for (int seg = 0; seg < 2; seg++) {
        const float* A = seg ? A2 : A1;
        const float* W = seg ? W2 : W1;
        int K = seg ? K2 : K1;
        if (A == nullptr) continue;
#pragma unroll 1
        for (int k0 = 0; k0 < K; k0 += BK) {
            // ---- stage A tile (128 x 32 fp32 -> hi/lo bf16) ----
#pragma unroll
            for (int p = 0; p < 4; p++) {
                int idx = tid + p * 256;          // 0..1023
                int row = idx >> 3;
                int c4  = idx & 7;                // float4 column
                int grow = brow + row;
                float4 v = make_float4(0.f, 0.f, 0.f, 0.f);
                if (grow < M)
                    v = *reinterpret_cast<const float4*>(A + (size_t)grow * K + k0 + c4 * 4);
                float hx = __bfloat162float(__float2bfloat16(v.x));
                float hy = __bfloat162float(__float2bfloat16(v.y));
                float hz = __bfloat162float(__float2bfloat16(v.z));
                float hw = __bfloat162float(__float2bfloat16(v.w));
                int w = row * 20 + c4 * 2;
                AsH32[w]     = pack_bf16(hx, hy);
                AsH32[w + 1] = pack_bf16(hz, hw);
                AsL32[w]     = pack_bf16(v.x - hx, v.y - hy);
                AsL32[w + 1] = pack_bf16(v.z - hz, v.w - hw);
            }
            // ---- stage W tile (32 x 64 fp32 -> transposed hi/lo bf16 [n][k]) ----
#pragma unroll
            for (int p = 0; p < 2; p++) {
                int idx = tid + p * 256;          // 0..511
                int k  = idx >> 4;                // 0..31
                int n4 = (idx & 15) * 4;          // 0..60
                float4 v = *reinterpret_cast<const float4*>(W + (size_t)(k0 + k) * N + bcol + n4);
                float hv[4], lv[4];
                hv[0] = __bfloat162float(__float2bfloat16(v.x)); lv[0] = v.x - hv[0];
                hv[1] = __bfloat162float(__float2bfloat16(v.y)); lv[1] = v.y - hv[1];
                hv[2] = __bfloat162float(__float2bfloat16(v.z)); lv[2] = v.z - hv[2];
                hv[3] = __bfloat162float(__float2bfloat16(v.w)); lv[3] = v.w - hv[3];
#pragma unroll
                for (int j = 0; j < 4; j++) {
                    BsH[(n4 + j) * SROW + k] = __float2bfloat16(hv[j]);
                    BsL[(n4 + j) * SROW + k] = __float2bfloat16(lv[j]);
                }
            }
            __syncthreads();

            // ---- compute: 2 k-steps of 16 ----
#pragma unroll
            for (int ks = 0; ks < 2; ks++) {
                int kw = ks * 8 + (lane & 3);
                uint32_t aH[2][4], aL[2][4], bH[4][2], bL[4][2];
#pragma unroll
                for (int mt = 0; mt < 2; mt++) {
                    int r = wm + mt * 16 + (lane >> 2);
                    aH[mt][0] = AsH32[r * 20 + kw];
                    aH[mt][1] = AsH32[(r + 8) * 20 + kw];
                    aH[mt][2] = AsH32[r * 20 + kw + 4];
                    aH[mt][3] = AsH32[(r + 8) * 20 + kw + 4];
                    aL[mt][0] = AsL32[r * 20 + kw];
                    aL[mt][1] = AsL32[(r + 8) * 20 + kw];
                    aL[mt][2] = AsL32[r * 20 + kw + 4];
                    aL[mt][3] = AsL32[(r + 8) * 20 + kw + 4];
                }
#pragma unroll
                for (int nt = 0; nt < 4; nt++) {
                    int n = wn + nt * 8 + (lane >> 2);
                    bH[nt][0] = BsH32[n * 20 + kw];
                    bH[nt][1] = BsH32[n * 20 + kw + 4];
                    bL[nt][0] = BsL32[n * 20 + kw];
                    bL[nt][1] = BsL32[n * 20 + kw + 4];
                }
#pragma unroll
                for (int mt = 0; mt < 2; mt++)
#pragma unroll
                    for (int nt = 0; nt < 4; nt++) {
                        mma_bf16(acc[mt][nt], aH[mt], bH[nt]);
                        mma_bf16(acc[mt][nt], aH[mt], bL[nt]);
                        mma_bf16(acc[mt][nt], aL[mt], bH[nt]);
                    }
            }
            __syncthreads();
        }
    }

    // ---- epilogue ----
#pragma unroll
    for (int mt = 0; mt < 2; mt++) {
#pragma unroll
        for (int nt = 0; nt < 4; nt++) {
            int r0 = brow + wm + mt * 16 + (lane >> 2);
            int c  = bcol + wn + nt * 8 + (lane & 3) * 2;
#pragma unroll
            for (int half = 0; half < 2; half++) {
                int row = r0 + half * 8;
                if (row >= M) continue;
                float v0 = acc[mt][nt][half * 2 + 0];
                float v1 = acc[mt][nt][half * 2 + 1];
                if (add) {
                    const float2 a2 = *reinterpret_cast<const float2*>(add + (size_t)row * N + c);
                    v0 += a2.x; v1 += a2.y;
                }
                if (bias) {
                    const float2 b2 = *reinterpret_cast<const float2*>(bias + c);
                    v0 += b2.x; v1 += b2.y;
                }
                if (leaky) { v0 = lrelu(v0); v1 = lrelu(v1); }
                *reinterpret_cast<float2*>(C + (size_t)row * N + c) = make_float2(v0, v1);
            }
        }
    }
}

// ---------------- pooling + logits ------------------------------------------------
__global__ void pool_kernel(const float* __restrict__ latent, const int* __restrict__ batch,
                            float* __restrict__ pooled) {
    int i = blockIdx.x * blockDim.x + threadIdx.x;  // node*64 + c4
    if (i >= N_NODES * 64) return;
    int node = i >> 6, c = i & 63;
    int g = batch[node];
    float4 v = reinterpret_cast<const float4*>(latent)[(size_t)node * 64 + c];
    red_add_v4(reinterpret_cast<float4*>(pooled) + (size_t)g * 64 + c, v);
}

__global__ void count_kernel(const int* __restrict__ batch, float* __restrict__ counts) {
    int i = blockIdx.x * blockDim.x + threadIdx.x;
    if (i < N_NODES) atomicAdd(&counts[batch[i]], 1.0f);
}

__global__ void logits_kernel(const float* __restrict__ pooled, const float* __restrict__ counts,
                              const float* __restrict__ w_lin, const float* __restrict__ b_lin,
                              float* __restrict__ out) {
    int g = blockIdx.x;
    int o = threadIdx.x;
    if (o >= OUT_CLS) return;
    float inv = 1.0f / fmaxf(counts[g], 1.0f);
    float s = 0.f;
    const float* pr = pooled + g * 256;
    for (int k = 0; k < 256; k++) s += pr[k] * w_lin[k * OUT_CLS + o];
    out[g * OUT_CLS + o] = s * inv + b_lin[o];
}

// ---------------- host launch -----------------------------------------------------
static inline void zero_buf(float* p, int nfloats) {
    int n4 = nfloats / 4;
    zero4_kernel<<<(n4 + 255) / 256, 256>>>(reinterpret_cast<float4*>(p), n4);
}

extern "C" void kernel_launch(void* const* d_in, const int* in_sizes, int n_in,
                              void* d_out, int out_size) {
    const int*   x       = (const int*)d_in[0];
    const int*   ei      = (const int*)d_in[1];
    const int*   batch   = (const int*)d_in[2];
    const float* emb     = (const float*)d_in[3];
    const float* w1_rel  = (const float*)d_in[4];
    const float* w1_root = (const float*)d_in[5];
    const float* b1      = (const float*)d_in[6];
    const float* w2_rel  = (const float*)d_in[7];
    const float* w2_root = (const float*)d_in[8];
    const float* b2      = (const float*)d_in[9];
    const float* we_rel  = (const float*)d_in[10];
    const float* we_root = (const float*)d_in[11];
    const float* be      = (const float*)d_in[12];
    const float* wd_rel  = (const float*)d_in[13];
    const float* wd_root = (const float*)d_in[14];
    const float* bd      = (const float*)d_in[15];
    const float* w_lin   = (const float*)d_in[16];
    const float* b_lin   = (const float*)d_in[17];

    const int* src = ei;
    const int* dst = ei + N_EDGES;

    float* out    = (float*)d_out;
    float* logits = out;
    float* recon  = out + OFF_RECON;
    float* orig   = out + OFF_ORIG;

    float *h0, *aggr0, *h1, *aggr1, *bufA, *bufB, *lat, *pool, *cnt;
    cudaGetSymbolAddress((void**)&h0,    g_h0);
    cudaGetSymbolAddress((void**)&aggr0, g_aggr0);
    cudaGetSymbolAddress((void**)&h1,    g_h1);
    cudaGetSymbolAddress((void**)&aggr1, g_aggr1);
    cudaGetSymbolAddress((void**)&bufA,  g_bufA);
    cudaGetSymbolAddress((void**)&bufB,  g_bufB);
    cudaGetSymbolAddress((void**)&lat,   g_lat);
    cudaGetSymbolAddress((void**)&pool,  g_pool);
    cudaGetSymbolAddress((void**)&cnt,   g_cnt);

    // ---- embed + conv1 ----
    embed_kernel<<<(N_NODES + 255) / 256, 256>>>(x, emb, h0);
    zero_buf(aggr0, N_NODES * 3);
    edge3_kernel<<<(N_EDGES + 255) / 256, 256>>>(h0, aggr0, src, dst);
    conv1_kernel<<<(N_NODES * 64 + 255) / 256, 256>>>(aggr0, h0, w1_rel, w1_root, b1, h1);

    // ---- conv2: original = leaky(aggr(h1)@w2_rel + h1@w2_root + b2) ----
    zero_buf(aggr1, N_NODES * 64);
    {
        int total = N_EDGES * 16;
        edge_agg_v4<<<(total + 255) / 256, 256>>>(h1, aggr1, src, dst, 4, total);
    }
    {
        dim3 grid(1024 / BN, (N_NODES + BM - 1) / BM);
        gemm_bf16_dual<<<grid, 256>>>(aggr1, w2_rel, 64, h1, w2_root, 64,
                                      nullptr, b2, orig, N_NODES, 1024, 1);
    }

    // ---- enc: latent = leaky(aggr(orig@we_rel) + orig@we_root + be) ----
    {
        dim3 grid(256 / BN, (N_NODES + BM - 1) / BM);
        gemm_bf16_dual<<<grid, 256>>>(orig, we_rel, 1024, nullptr, nullptr, 0,
                                      nullptr, nullptr, bufA, N_NODES, 256, 0);
    }
    zero_buf(bufB, N_NODES * 256);
    {
        int total = N_EDGES * 64;
        edge_agg_v4<<<(total + 255) / 256, 256>>>(bufA, bufB, src, dst, 6, total);
    }
    {
        dim3 grid(256 / BN, (N_NODES + BM - 1) / BM);
        gemm_bf16_dual<<<grid, 256>>>(orig, we_root, 1024, nullptr, nullptr, 0,
                                      bufB, be, lat, N_NODES, 256, 1);
    }

    // ---- pool + logits ----
    zero_buf(pool, N_GRAPHS * 256);
    zero_buf(cnt, N_GRAPHS);
    pool_kernel<<<(N_NODES * 64 + 255) / 256, 256>>>(lat, batch, pool);
    count_kernel<<<(N_NODES + 255) / 256, 256>>>(batch, cnt);
    logits_kernel<<<N_GRAPHS, 32>>>(pool, cnt, w_lin, b_lin, logits);

    // ---- dec: recon = leaky(aggr(latent)@wd_rel + latent@wd_root + bd) ----
    zero_buf(bufA, N_NODES * 256);
    {
        int total = N_EDGES * 64;
        edge_agg_v4<<<(total + 255) / 256, 256>>>(lat, bufA, src, dst, 6, total);
    }
    {
        dim3 grid(1024 / BN, (N_NODES + BM - 1) / BM);
        gemm_bf16_dual<<<grid, 256>>>(bufA, wd_rel, 256, lat, wd_root, 256,
                                      nullptr, bd, recon, N_NODES, 1024, 1);
    }
}